// round 1
// baseline (speedup 1.0000x reference)
#include <cuda_runtime.h>
#include <cuda_bf16.h>
#include <cstdint>
#include <cstddef>

// ---------------------------------------------------------------------------
// Problem constants (fixed shapes per reference): D=128, A=64
// ---------------------------------------------------------------------------
static constexpr size_t MAXN = 200000;
static constexpr size_t MAXB = 256;

// Scratch (device globals; no runtime allocation allowed)
__device__ float g_Xs  [MAXN * 64];     // hidden @ Ws^T
__device__ float g_agg [MAXN * 128];    // segment sum
__device__ float g_hnew[MAXN * 128];    // relu(agg @ W_h^T)
__device__ float g_gi  [MAXN * 384];    // h_new @ W_ih^T + b_ih
__device__ float g_PR  [128 * 64];      // rel_emb @ Wr^T   (R<=128)
__device__ float g_PQb [MAXB * 64];     // rel_emb[q_rel[b]] @ Wqr^T + b_qr
__device__ float g_Wst [128 * 64];      // Ws  transposed  [k][a]
__device__ float g_Wrt [128 * 64];      // Wr  transposed
__device__ float g_Wqrt[128 * 64];      // Wqr transposed
__device__ float g_Wht [128 * 128];     // W_h transposed  [k][c]
__device__ float g_Wiht[128 * 384];     // W_ih transposed [k][c]
__device__ int   g_h0nz;

// ---------------------------------------------------------------------------
// Tiny setup kernels
// ---------------------------------------------------------------------------
__global__ void k_flag0(int* flag) { *flag = 0; }

// zero agg (float4) and scan h0 for nonzeros, in one pass over N*128 floats
__global__ void k_zero_scan(float* agg, const float* __restrict__ h0, int nquads, int* flag)
{
    int i = blockIdx.x * blockDim.x + threadIdx.x;
    int stride = gridDim.x * blockDim.x;
    bool nz = false;
    float4 z = make_float4(0.f, 0.f, 0.f, 0.f);
    for (; i < nquads; i += stride) {
        reinterpret_cast<float4*>(agg)[i] = z;
        float4 v = reinterpret_cast<const float4*>(h0)[i];
        nz |= (v.x != 0.f) | (v.y != 0.f) | (v.z != 0.f) | (v.w != 0.f);
    }
    if (nz) atomicOr(flag, 1);
}

// out[c*rows + r] = in[r*cols + c]   (weights are tiny; simplicity over speed)
__global__ void k_transpose(const float* __restrict__ in, float* __restrict__ out,
                            int rows, int cols)
{
    int i = blockIdx.x * blockDim.x + threadIdx.x;
    if (i < rows * cols) {
        int r = i / cols, c = i % cols;
        out[(size_t)c * rows + r] = in[(size_t)r * cols + c];
    }
}

// PR[r][a] = dot(rel_emb[r], Wr[a]);  PQb[b][a] = dot(rel_emb[q_rel[b]], Wqr[a]) + b_qr[a]
__global__ void k_prep(const float* __restrict__ rel_emb,
                       const float* __restrict__ b_qr,
                       const int*   __restrict__ q_rel,
                       const float* __restrict__ Wrt,   // [128][64]
                       const float* __restrict__ Wqrt,  // [128][64]
                       float* __restrict__ PR, float* __restrict__ PQb,
                       int Rv, int Bv)
{
    __shared__ float se[128];
    int blk = blockIdx.x;
    int a = threadIdx.x;   // 0..63
    int r;
    const float* Wt;
    float* dst;
    float bias;
    if (blk < Rv) { r = blk;               Wt = Wrt;  dst = PR  + (size_t)blk * 64;        bias = 0.f; }
    else          { int b = blk - Rv; r = q_rel[b]; Wt = Wqrt; dst = PQb + (size_t)b * 64; bias = b_qr[a]; }
    se[a]      = rel_emb[(size_t)r * 128 + a];
    se[a + 64] = rel_emb[(size_t)r * 128 + a + 64];
    __syncthreads();
    float acc = bias;
    #pragma unroll 8
    for (int k = 0; k < 128; k++) acc += se[k] * Wt[k * 64 + a];
    dst[a] = acc;
}

// ---------------------------------------------------------------------------
// Tiled GEMM: C[m, col0 + c] = (relu?)(A[m,:128] . Wt[:, col0 + c] (+bias))
// A: [M][128] row-major.  Wt: [128][ldw] row-major (pre-transposed weights).
// BM=64, block 256 threads (16x16), each thread computes 4 rows x (BN/16) cols.
// ---------------------------------------------------------------------------
template<int BN, bool RELU, bool BIAS>
__global__ void k_gemm(const float* __restrict__ A, const float* __restrict__ Wt,
                       const float* __restrict__ bias, float* __restrict__ C,
                       int M, int ldw, int ldc, int col0base)
{
    extern __shared__ float sm[];
    float* sA = sm;               // [64][128]
    float* sW = sm + 64 * 128;    // [128][BN]
    const int t  = threadIdx.x;
    const int tx = t & 15, ty = t >> 4;
    const int m0 = blockIdx.x * 64;
    const int col0 = col0base + blockIdx.y * BN;

    // stage A tile (coalesced float4, conflict-free)
    {
        const float4* Ag = reinterpret_cast<const float4*>(A) + (size_t)m0 * 32;
        float4* sA4 = reinterpret_cast<float4*>(sA);
        #pragma unroll
        for (int i = 0; i < 8; i++) {
            int f = t + i * 256;            // quad index: row = f>>5, qc = f&31
            int row = f >> 5;
            sA4[f] = (m0 + row < M) ? Ag[(size_t)row * 32 + (f & 31)]
                                    : make_float4(0.f, 0.f, 0.f, 0.f);
        }
    }
    // stage W tile (coalesced float4, conflict-free; Wt already k-major)
    {
        constexpr int QPB = BN / 4;         // quads per k-row
        float4* sW4 = reinterpret_cast<float4*>(sW);
        #pragma unroll
        for (int f = t; f < 32 * BN; f += 256) {
            int k = f / QPB, qc = f % QPB;
            sW4[(size_t)k * QPB + qc] =
                *reinterpret_cast<const float4*>(Wt + (size_t)k * ldw + col0 + qc * 4);
        }
    }
    __syncthreads();

    constexpr int CPT = BN / 16;   // 4 or 8 cols per thread
    float acc[4][CPT];
    #pragma unroll
    for (int i = 0; i < 4; i++)
        #pragma unroll
        for (int j = 0; j < CPT; j++) acc[i][j] = 0.f;

    #pragma unroll 4
    for (int k = 0; k < 128; k++) {
        float a0 = sA[(ty * 4 + 0) * 128 + k];    // broadcast loads
        float a1 = sA[(ty * 4 + 1) * 128 + k];
        float a2 = sA[(ty * 4 + 2) * 128 + k];
        float a3 = sA[(ty * 4 + 3) * 128 + k];
        float b[CPT];
        #pragma unroll
        for (int j = 0; j < CPT; j += 4) {
            float4 b4 = *reinterpret_cast<const float4*>(&sW[k * BN + tx * CPT + j]);
            b[j] = b4.x; b[j + 1] = b4.y; b[j + 2] = b4.z; b[j + 3] = b4.w;
        }
        #pragma unroll
        for (int j = 0; j < CPT; j++) {
            acc[0][j] += a0 * b[j];
            acc[1][j] += a1 * b[j];
            acc[2][j] += a2 * b[j];
            acc[3][j] += a3 * b[j];
        }
    }

    #pragma unroll
    for (int i = 0; i < 4; i++) {
        int m = m0 + ty * 4 + i;
        if (m >= M) continue;
        #pragma unroll
        for (int j = 0; j < CPT; j++) {
            float v = acc[i][j];
            int c = col0 + tx * CPT + j;
            if (BIAS) v += bias[c];
            if (RELU) v = fmaxf(v, 0.f);
            C[(size_t)m * ldc + c] = v;
        }
    }
}

// ---------------------------------------------------------------------------
// Edge kernel: one warp per edge.
//   att[a] = relu(Xs[sub][a] + PR[rel][a] + PQb[batch][a])        (a = lane, lane+32)
//   alpha  = sigmoid(att . w_alpha + b_alpha)
//   atomicAdd(agg[obj], alpha * (hidden[sub] + rel_emb[rel]))     (float4 RED)
// ---------------------------------------------------------------------------
__global__ void k_edge(const float* __restrict__ hidden, const float* __restrict__ rel_emb,
                       const float* __restrict__ w_alpha, const float* __restrict__ b_alpha,
                       const int* __restrict__ sub, const int* __restrict__ rel,
                       const int* __restrict__ obj, const int* __restrict__ ebatch,
                       const float* __restrict__ Xs, const float* __restrict__ PR,
                       const float* __restrict__ PQb, float* __restrict__ agg, int E)
{
    int warp = (blockIdx.x * blockDim.x + threadIdx.x) >> 5;
    int lane = threadIdx.x & 31;
    if (warp >= E) return;
    int s = sub[warp], r = rel[warp], o = obj[warp], b = ebatch[warp];

    float att0 = Xs[(size_t)s * 64 + lane]      + PR[r * 64 + lane]      + PQb[b * 64 + lane];
    float att1 = Xs[(size_t)s * 64 + lane + 32] + PR[r * 64 + lane + 32] + PQb[b * 64 + lane + 32];
    att0 = fmaxf(att0, 0.f);
    att1 = fmaxf(att1, 0.f);
    float p = att0 * w_alpha[lane] + att1 * w_alpha[lane + 32];
    #pragma unroll
    for (int off = 16; off; off >>= 1) p += __shfl_xor_sync(0xffffffffu, p, off);
    float alpha = 1.f / (1.f + __expf(-(p + b_alpha[0])));

    float4 h  = reinterpret_cast<const float4*>(hidden  + (size_t)s * 128)[lane];
    float4 rr = reinterpret_cast<const float4*>(rel_emb + (size_t)r * 128)[lane];
    float4 m  = make_float4(alpha * (h.x + rr.x), alpha * (h.y + rr.y),
                            alpha * (h.z + rr.z), alpha * (h.w + rr.w));
    atomicAdd(reinterpret_cast<float4*>(agg + (size_t)o * 128) + lane, m);
}

// ---------------------------------------------------------------------------
// GRU gate + final score: one warp per node; lane owns cols j = lane + m*32.
// gi already contains h_new@W_ih^T + b_ih. If h0 == 0 (flag): gh = b_hh and
// h_out = (1-z)*n; else full (slow, correct) path.
// ---------------------------------------------------------------------------
__global__ void k_gru(const float* __restrict__ gi_buf,
                      const float* __restrict__ b_hh, const float* __restrict__ W_hh,
                      const float* __restrict__ h0,   const float* __restrict__ W_final,
                      const int* __restrict__ flag, float* __restrict__ out, int Nn)
{
    int warp = (blockIdx.x * blockDim.x + threadIdx.x) >> 5;
    int lane = threadIdx.x & 31;
    if (warp >= Nn) return;
    const float* gi = gi_buf + (size_t)warp * 384;
    int nzflag = *flag;
    float acc = 0.f;
    #pragma unroll
    for (int m = 0; m < 4; m++) {
        int j = lane + m * 32;
        float ir  = gi[j], iz = gi[128 + j], in_ = gi[256 + j];
        float hr  = b_hh[j], hz = b_hh[128 + j], hn = b_hh[256 + j];
        float h0v = 0.f;
        if (nzflag) {
            h0v = h0[(size_t)warp * 128 + j];
            float dr = 0.f, dz = 0.f, dn = 0.f;
            for (int k = 0; k < 128; k++) {
                float hv = h0[(size_t)warp * 128 + k];
                dr += W_hh[(size_t)j * 128 + k] * hv;
                dz += W_hh[(size_t)(128 + j) * 128 + k] * hv;
                dn += W_hh[(size_t)(256 + j) * 128 + k] * hv;
            }
            hr += dr; hz += dz; hn += dn;
        }
        float rg = 1.f / (1.f + __expf(-(ir + hr)));
        float zg = 1.f / (1.f + __expf(-(iz + hz)));
        float ng = tanhf(in_ + rg * hn);
        float h  = (1.f - zg) * ng + zg * h0v;
        acc += h * W_final[j];
    }
    #pragma unroll
    for (int off = 16; off; off >>= 1) acc += __shfl_xor_sync(0xffffffffu, acc, off);
    if (lane == 0) out[warp] = acc;
}

// ---------------------------------------------------------------------------
// Launch
// ---------------------------------------------------------------------------
extern "C" void kernel_launch(void* const* d_in, const int* in_sizes, int n_in,
                              void* d_out, int out_size)
{
    const float* hidden  = (const float*)d_in[0];
    const float* rel_emb = (const float*)d_in[1];
    const float* Ws      = (const float*)d_in[2];
    const float* Wr      = (const float*)d_in[3];
    const float* Wqr     = (const float*)d_in[4];
    const float* b_qr    = (const float*)d_in[5];
    const float* w_alpha = (const float*)d_in[6];
    const float* b_alpha = (const float*)d_in[7];
    const float* W_h     = (const float*)d_in[8];
    const float* W_ih    = (const float*)d_in[9];
    const float* W_hh    = (const float*)d_in[10];
    const float* b_ih    = (const float*)d_in[11];
    const float* b_hh    = (const float*)d_in[12];
    const float* W_final = (const float*)d_in[13];
    const float* h0      = (const float*)d_in[14];
    const int*   sub     = (const int*)d_in[15];
    const int*   rel     = (const int*)d_in[16];
    const int*   obj     = (const int*)d_in[17];
    const int*   ebatch  = (const int*)d_in[18];
    const int*   q_rel   = (const int*)d_in[19];
    float*       out     = (float*)d_out;

    const int Nn = in_sizes[0] / 128;
    const int Rv = in_sizes[1] / 128;
    const int Ev = in_sizes[15];
    const int Bv = in_sizes[19];

    // device-global scratch addresses (module-lifetime; stable across replays)
    float *pXs, *pAgg, *pHnew, *pGi, *pPR, *pPQb, *pWst, *pWrt, *pWqrt, *pWht, *pWiht;
    int* pFlag;
    cudaGetSymbolAddress((void**)&pXs,   g_Xs);
    cudaGetSymbolAddress((void**)&pAgg,  g_agg);
    cudaGetSymbolAddress((void**)&pHnew, g_hnew);
    cudaGetSymbolAddress((void**)&pGi,   g_gi);
    cudaGetSymbolAddress((void**)&pPR,   g_PR);
    cudaGetSymbolAddress((void**)&pPQb,  g_PQb);
    cudaGetSymbolAddress((void**)&pWst,  g_Wst);
    cudaGetSymbolAddress((void**)&pWrt,  g_Wrt);
    cudaGetSymbolAddress((void**)&pWqrt, g_Wqrt);
    cudaGetSymbolAddress((void**)&pWht,  g_Wht);
    cudaGetSymbolAddress((void**)&pWiht, g_Wiht);
    cudaGetSymbolAddress((void**)&pFlag, g_h0nz);

    // dynamic smem opt-in for GEMM instantiations (idempotent)
    const int SM64  = (64 * 128 + 128 * 64)  * (int)sizeof(float);   // 64 KB
    const int SM128 = (64 * 128 + 128 * 128) * (int)sizeof(float);   // 96 KB
    cudaFuncSetAttribute(k_gemm<64,  false, false>, cudaFuncAttributeMaxDynamicSharedMemorySize, SM64);
    cudaFuncSetAttribute(k_gemm<128, true,  false>, cudaFuncAttributeMaxDynamicSharedMemorySize, SM128);
    cudaFuncSetAttribute(k_gemm<128, false, true >, cudaFuncAttributeMaxDynamicSharedMemorySize, SM128);

    // 1) flag reset, zero agg + scan h0
    k_flag0<<<1, 1>>>(pFlag);
    k_zero_scan<<<2048, 256>>>(pAgg, h0, Nn * 32, pFlag);

    // 2) weight transposes (k-major layout for GEMM staging)
    k_transpose<<<(64  * 128 + 255) / 256, 256>>>(Ws,   pWst,  64,  128);
    k_transpose<<<(64  * 128 + 255) / 256, 256>>>(Wr,   pWrt,  64,  128);
    k_transpose<<<(64  * 128 + 255) / 256, 256>>>(Wqr,  pWqrt, 64,  128);
    k_transpose<<<(128 * 128 + 255) / 256, 256>>>(W_h,  pWht,  128, 128);
    k_transpose<<<(384 * 128 + 255) / 256, 256>>>(W_ih, pWiht, 384, 128);

    // 3) PR / PQb precompute
    k_prep<<<Rv + Bv, 64>>>(rel_emb, b_qr, q_rel, pWrt, pWqrt, pPR, pPQb, Rv, Bv);

    // 4) Xs = hidden @ Ws^T   [N,64]
    int mtiles = (Nn + 63) / 64;
    k_gemm<64, false, false><<<dim3(mtiles, 1), 256, SM64>>>(hidden, pWst, nullptr, pXs, Nn, 64, 64, 0);

    // 5) edge message passing + segment sum
    k_edge<<<(Ev + 7) / 8, 256>>>(hidden, rel_emb, w_alpha, b_alpha,
                                  sub, rel, obj, ebatch, pXs, pPR, pPQb, pAgg, Ev);

    // 6) h_new = relu(agg @ W_h^T)   [N,128]
    k_gemm<128, true, false><<<dim3(mtiles, 1), 256, SM128>>>(pAgg, pWht, nullptr, pHnew, Nn, 128, 128, 0);

    // 7) gi = h_new @ W_ih^T + b_ih  [N,384]  (3 column tiles of 128)
    k_gemm<128, false, true><<<dim3(mtiles, 3), 256, SM128>>>(pHnew, pWiht, b_ih, pGi, Nn, 384, 384, 0);

    // 8) GRU gate + final score
    k_gru<<<(Nn + 7) / 8, 256>>>(pGi, b_hh, W_hh, h0, W_final, pFlag, out, Nn);
}

// round 2
// speedup vs baseline: 1.9784x; 1.9784x over previous
#include <cuda_runtime.h>
#include <cuda_bf16.h>
#include <cstdint>
#include <cstddef>

// ---------------------------------------------------------------------------
// Fixed shapes: D=128 (K2=64 bf16 pairs), A=64
// ---------------------------------------------------------------------------
static constexpr size_t MAXN = 200000;
static constexpr size_t MAXB = 256;

// Scratch (device globals; no runtime allocation allowed)
__device__ float    g_Xs  [MAXN * 64];     // hidden @ Ws^T
__device__ float    g_agg [MAXN * 128];    // segment sum
__device__ float    g_hnew[MAXN * 128];    // relu(agg @ W_h^T)
__device__ float    g_gi  [MAXN * 384];    // h_new @ W_ih^T + b_ih
__device__ float    g_PR  [128 * 64];      // rel_emb @ Wr^T   (R<=128)
__device__ float    g_PQb [MAXB * 64];     // rel_emb[q_rel[b]] @ Wqr^T + b_qr
__device__ float    g_Wrt [128 * 64];      // Wr  transposed fp32 (for k_prep)
__device__ float    g_Wqrt[128 * 64];      // Wqr transposed fp32
// bf16-split weights, k2-major pairs: entry [k2][c] = {W[c][2k2], W[c][2k2+1]}
__device__ uint32_t g_WsH [64 * 64],  g_WsL [64 * 64];
__device__ uint32_t g_WhH [64 * 128], g_WhL [64 * 128];
__device__ uint32_t g_WihH[64 * 384], g_WihL[64 * 384];
__device__ int      g_h0nz;

// ---------------------------------------------------------------------------
// Helpers
// ---------------------------------------------------------------------------
__device__ __forceinline__ uint32_t pack_bf2(__nv_bfloat16 a, __nv_bfloat16 b)
{
    __nv_bfloat162 h; h.x = a; h.y = b;
    return *reinterpret_cast<uint32_t*>(&h);
}

__device__ __forceinline__ void split2(float x, float y, uint32_t& hi, uint32_t& lo)
{
    __nv_bfloat16 hx = __float2bfloat16_rn(x), hy = __float2bfloat16_rn(y);
    float rx = x - __bfloat162float(hx);
    float ry = y - __bfloat162float(hy);
    hi = pack_bf2(hx, hy);
    lo = pack_bf2(__float2bfloat16_rn(rx), __float2bfloat16_rn(ry));
}

__device__ __forceinline__ void mma_bf16(float* c, uint32_t a0, uint32_t a1,
                                         uint32_t a2, uint32_t a3,
                                         uint32_t b0, uint32_t b1)
{
    asm volatile(
        "mma.sync.aligned.m16n8k16.row.col.f32.bf16.bf16.f32 "
        "{%0,%1,%2,%3}, {%4,%5,%6,%7}, {%8,%9}, {%0,%1,%2,%3};\n"
        : "+f"(c[0]), "+f"(c[1]), "+f"(c[2]), "+f"(c[3])
        : "r"(a0), "r"(a1), "r"(a2), "r"(a3), "r"(b0), "r"(b1));
}

// ---------------------------------------------------------------------------
// Tiny setup kernels
// ---------------------------------------------------------------------------
__global__ void k_flag0(int* flag) { *flag = 0; }

__global__ void k_zero_scan(float* agg, const float* __restrict__ h0, int nquads, int* flag)
{
    int i = blockIdx.x * blockDim.x + threadIdx.x;
    int stride = gridDim.x * blockDim.x;
    bool nz = false;
    float4 z = make_float4(0.f, 0.f, 0.f, 0.f);
    for (; i < nquads; i += stride) {
        reinterpret_cast<float4*>(agg)[i] = z;
        float4 v = reinterpret_cast<const float4*>(h0)[i];
        nz |= (v.x != 0.f) | (v.y != 0.f) | (v.z != 0.f) | (v.w != 0.f);
    }
    if (nz) atomicOr(flag, 1);
}

__global__ void k_transpose(const float* __restrict__ in, float* __restrict__ out,
                            int rows, int cols)
{
    int i = blockIdx.x * blockDim.x + threadIdx.x;
    if (i < rows * cols) {
        int r = i / cols, c = i % cols;
        out[(size_t)c * rows + r] = in[(size_t)r * cols + c];
    }
}

// Split W[rows][128] (fp32, row-major) into k2-major bf16-pair hi/lo [64][rows]
__global__ void k_prep_w(const float* __restrict__ W, uint32_t* __restrict__ hi,
                         uint32_t* __restrict__ lo, int rows)
{
    int i = blockIdx.x * blockDim.x + threadIdx.x;
    if (i >= 64 * rows) return;
    int k2 = i / rows, c = i % rows;
    float x = W[(size_t)c * 128 + 2 * k2];
    float y = W[(size_t)c * 128 + 2 * k2 + 1];
    uint32_t h, l;
    split2(x, y, h, l);
    hi[(size_t)k2 * rows + c] = h;
    lo[(size_t)k2 * rows + c] = l;
}

// PR[r][a] = dot(rel_emb[r], Wr[a]);  PQb[b][a] = dot(rel_emb[q_rel[b]], Wqr[a]) + b_qr[a]
__global__ void k_prep(const float* __restrict__ rel_emb,
                       const float* __restrict__ b_qr,
                       const int*   __restrict__ q_rel,
                       const float* __restrict__ Wrt,   // [128][64] fp32
                       const float* __restrict__ Wqrt,  // [128][64] fp32
                       float* __restrict__ PR, float* __restrict__ PQb,
                       int Rv, int Bv)
{
    __shared__ float se[128];
    int blk = blockIdx.x;
    int a = threadIdx.x;   // 0..63
    int r;
    const float* Wt;
    float* dst;
    float bias;
    if (blk < Rv) { r = blk;               Wt = Wrt;  dst = PR  + (size_t)blk * 64;        bias = 0.f; }
    else          { int b = blk - Rv; r = q_rel[b]; Wt = Wqrt; dst = PQb + (size_t)b * 64; bias = b_qr[a]; }
    se[a]      = rel_emb[(size_t)r * 128 + a];
    se[a + 64] = rel_emb[(size_t)r * 128 + a + 64];
    __syncthreads();
    float acc = bias;
    #pragma unroll 8
    for (int k = 0; k < 128; k++) acc += se[k] * Wt[k * 64 + a];
    dst[a] = acc;
}

// ---------------------------------------------------------------------------
// Tensor-core GEMM via 3-term bf16 split (error ~2^-16, far under 1e-3):
//   C[m, col0+c] = op( A[m,:128] . W^T[:, col0+c] )   A fp32, W pre-split bf16
// BM=64, 256 threads, 8 warps: warp (w&3) -> 16-row tile, (w>>2) -> BN/2 cols.
// Smem strides padded +8 u32 -> conflict-free fragment loads.
// ---------------------------------------------------------------------------
template<int BN, bool RELU, bool BIAS>
__global__ void k_gemm_mma(const float* __restrict__ A,
                           const uint32_t* __restrict__ Bhi,
                           const uint32_t* __restrict__ Blo,
                           const float* __restrict__ bias,
                           float* __restrict__ C,
                           int M, int ldw, int ldc)
{
    constexpr int AP = 72;        // padded u32 stride for A (K2=64)
    constexpr int BP = BN + 8;    // padded u32 stride for B
    extern __shared__ uint32_t sm[];
    uint32_t* sAh = sm;                       // [64][AP]
    uint32_t* sAl = sAh + 64 * AP;
    uint32_t* sBh = sAl + 64 * AP;            // [64][BP]
    uint32_t* sBl = sBh + 64 * BP;

    const int t    = threadIdx.x;
    const int m0   = blockIdx.x * 64;
    const int col0 = blockIdx.y * BN;

    // stage + split A (coalesced float2 = one bf16 k-pair)
    #pragma unroll
    for (int i = 0; i < 16; i++) {
        int f = t + i * 256;                  // 64*64 = 4096 pairs
        int row = f >> 6, k2 = f & 63;
        float2 v = (m0 + row < M)
                 ? reinterpret_cast<const float2*>(A)[(size_t)(m0 + row) * 64 + k2]
                 : make_float2(0.f, 0.f);
        uint32_t h, l;
        split2(v.x, v.y, h, l);
        sAh[row * AP + k2] = h;
        sAl[row * AP + k2] = l;
    }
    // stage B (already split in gmem)
    for (int f = t; f < 64 * BN; f += 256) {
        int k2 = f / BN, c = f % BN;
        sBh[k2 * BP + c] = Bhi[(size_t)k2 * ldw + col0 + c];
        sBl[k2 * BP + c] = Blo[(size_t)k2 * ldw + col0 + c];
    }
    __syncthreads();

    const int w = t >> 5, lane = t & 31;
    const int g = lane >> 2, tg = lane & 3;
    const int wm = (w & 3) * 16;
    const int wn = (w >> 2) * (BN / 2);
    constexpr int NT = BN / 16;               // n-tiles of 8 per warp

    float acc[NT][4];
    #pragma unroll
    for (int n = 0; n < NT; n++)
        #pragma unroll
        for (int j = 0; j < 4; j++) acc[n][j] = 0.f;

    #pragma unroll
    for (int kk = 0; kk < 64; kk += 8) {      // k16 per step
        uint32_t ah0 = sAh[(wm + g)     * AP + kk + tg];
        uint32_t ah1 = sAh[(wm + g + 8) * AP + kk + tg];
        uint32_t ah2 = sAh[(wm + g)     * AP + kk + tg + 4];
        uint32_t ah3 = sAh[(wm + g + 8) * AP + kk + tg + 4];
        uint32_t al0 = sAl[(wm + g)     * AP + kk + tg];
        uint32_t al1 = sAl[(wm + g + 8) * AP + kk + tg];
        uint32_t al2 = sAl[(wm + g)     * AP + kk + tg + 4];
        uint32_t al3 = sAl[(wm + g + 8) * AP + kk + tg + 4];
        #pragma unroll
        for (int n = 0; n < NT; n++) {
            int nc = wn + n * 8 + g;
            uint32_t bh0 = sBh[(kk + tg)     * BP + nc];
            uint32_t bh1 = sBh[(kk + tg + 4) * BP + nc];
            uint32_t bl0 = sBl[(kk + tg)     * BP + nc];
            uint32_t bl1 = sBl[(kk + tg + 4) * BP + nc];
            mma_bf16(acc[n], ah0, ah1, ah2, ah3, bh0, bh1);
            mma_bf16(acc[n], ah0, ah1, ah2, ah3, bl0, bl1);
            mma_bf16(acc[n], al0, al1, al2, al3, bh0, bh1);
        }
    }

    // epilogue (float2 stores; cols 2tg,2tg+1 are adjacent)
    const int row = m0 + wm + g;
    #pragma unroll
    for (int n = 0; n < NT; n++) {
        int cabs = col0 + wn + n * 8 + 2 * tg;
        float v0 = acc[n][0], v1 = acc[n][1], v2 = acc[n][2], v3 = acc[n][3];
        if (BIAS) {
            float b0 = bias[cabs], b1 = bias[cabs + 1];
            v0 += b0; v1 += b1; v2 += b0; v3 += b1;
        }
        if (RELU) {
            v0 = fmaxf(v0, 0.f); v1 = fmaxf(v1, 0.f);
            v2 = fmaxf(v2, 0.f); v3 = fmaxf(v3, 0.f);
        }
        if (row < M)
            *reinterpret_cast<float2*>(&C[(size_t)row * ldc + cabs]) = make_float2(v0, v1);
        if (row + 8 < M)
            *reinterpret_cast<float2*>(&C[(size_t)(row + 8) * ldc + cabs]) = make_float2(v2, v3);
    }
}

// ---------------------------------------------------------------------------
// Edge kernel: one warp per edge (unchanged from R1)
// ---------------------------------------------------------------------------
__global__ void k_edge(const float* __restrict__ hidden, const float* __restrict__ rel_emb,
                       const float* __restrict__ w_alpha, const float* __restrict__ b_alpha,
                       const int* __restrict__ sub, const int* __restrict__ rel,
                       const int* __restrict__ obj, const int* __restrict__ ebatch,
                       const float* __restrict__ Xs, const float* __restrict__ PR,
                       const float* __restrict__ PQb, float* __restrict__ agg, int E)
{
    int warp = (blockIdx.x * blockDim.x + threadIdx.x) >> 5;
    int lane = threadIdx.x & 31;
    if (warp >= E) return;
    int s = sub[warp], r = rel[warp], o = obj[warp], b = ebatch[warp];

    float att0 = Xs[(size_t)s * 64 + lane]      + PR[r * 64 + lane]      + PQb[b * 64 + lane];
    float att1 = Xs[(size_t)s * 64 + lane + 32] + PR[r * 64 + lane + 32] + PQb[b * 64 + lane + 32];
    att0 = fmaxf(att0, 0.f);
    att1 = fmaxf(att1, 0.f);
    float p = att0 * w_alpha[lane] + att1 * w_alpha[lane + 32];
    #pragma unroll
    for (int off = 16; off; off >>= 1) p += __shfl_xor_sync(0xffffffffu, p, off);
    float alpha = 1.f / (1.f + __expf(-(p + b_alpha[0])));

    float4 h  = reinterpret_cast<const float4*>(hidden  + (size_t)s * 128)[lane];
    float4 rr = reinterpret_cast<const float4*>(rel_emb + (size_t)r * 128)[lane];
    float4 m  = make_float4(alpha * (h.x + rr.x), alpha * (h.y + rr.y),
                            alpha * (h.z + rr.z), alpha * (h.w + rr.w));
    atomicAdd(reinterpret_cast<float4*>(agg + (size_t)o * 128) + lane, m);
}

// ---------------------------------------------------------------------------
// GRU gate + final score (unchanged from R1)
// ---------------------------------------------------------------------------
__global__ void k_gru(const float* __restrict__ gi_buf,
                      const float* __restrict__ b_hh, const float* __restrict__ W_hh,
                      const float* __restrict__ h0,   const float* __restrict__ W_final,
                      const int* __restrict__ flag, float* __restrict__ out, int Nn)
{
    int warp = (blockIdx.x * blockDim.x + threadIdx.x) >> 5;
    int lane = threadIdx.x & 31;
    if (warp >= Nn) return;
    const float* gi = gi_buf + (size_t)warp * 384;
    int nzflag = *flag;
    float acc = 0.f;
    #pragma unroll
    for (int m = 0; m < 4; m++) {
        int j = lane + m * 32;
        float ir  = gi[j], iz = gi[128 + j], in_ = gi[256 + j];
        float hr  = b_hh[j], hz = b_hh[128 + j], hn = b_hh[256 + j];
        float h0v = 0.f;
        if (nzflag) {
            h0v = h0[(size_t)warp * 128 + j];
            float dr = 0.f, dz = 0.f, dn = 0.f;
            for (int k = 0; k < 128; k++) {
                float hv = h0[(size_t)warp * 128 + k];
                dr += W_hh[(size_t)j * 128 + k] * hv;
                dz += W_hh[(size_t)(128 + j) * 128 + k] * hv;
                dn += W_hh[(size_t)(256 + j) * 128 + k] * hv;
            }
            hr += dr; hz += dz; hn += dn;
        }
        float rg = 1.f / (1.f + __expf(-(ir + hr)));
        float zg = 1.f / (1.f + __expf(-(iz + hz)));
        float ng = tanhf(in_ + rg * hn);
        float h  = (1.f - zg) * ng + zg * h0v;
        acc += h * W_final[j];
    }
    #pragma unroll
    for (int off = 16; off; off >>= 1) acc += __shfl_xor_sync(0xffffffffu, acc, off);
    if (lane == 0) out[warp] = acc;
}

// ---------------------------------------------------------------------------
// Launch
// ---------------------------------------------------------------------------
extern "C" void kernel_launch(void* const* d_in, const int* in_sizes, int n_in,
                              void* d_out, int out_size)
{
    const float* hidden  = (const float*)d_in[0];
    const float* rel_emb = (const float*)d_in[1];
    const float* Ws      = (const float*)d_in[2];
    const float* Wr      = (const float*)d_in[3];
    const float* Wqr     = (const float*)d_in[4];
    const float* b_qr    = (const float*)d_in[5];
    const float* w_alpha = (const float*)d_in[6];
    const float* b_alpha = (const float*)d_in[7];
    const float* W_h     = (const float*)d_in[8];
    const float* W_ih    = (const float*)d_in[9];
    const float* W_hh    = (const float*)d_in[10];
    const float* b_ih    = (const float*)d_in[11];
    const float* b_hh    = (const float*)d_in[12];
    const float* W_final = (const float*)d_in[13];
    const float* h0      = (const float*)d_in[14];
    const int*   sub     = (const int*)d_in[15];
    const int*   rel     = (const int*)d_in[16];
    const int*   obj     = (const int*)d_in[17];
    const int*   ebatch  = (const int*)d_in[18];
    const int*   q_rel   = (const int*)d_in[19];
    float*       out     = (float*)d_out;

    const int Nn = in_sizes[0] / 128;
    const int Rv = in_sizes[1] / 128;
    const int Ev = in_sizes[15];
    const int Bv = in_sizes[19];

    float *pXs, *pAgg, *pHnew, *pGi, *pPR, *pPQb, *pWrt, *pWqrt;
    uint32_t *pWsH, *pWsL, *pWhH, *pWhL, *pWihH, *pWihL;
    int* pFlag;
    cudaGetSymbolAddress((void**)&pXs,   g_Xs);
    cudaGetSymbolAddress((void**)&pAgg,  g_agg);
    cudaGetSymbolAddress((void**)&pHnew, g_hnew);
    cudaGetSymbolAddress((void**)&pGi,   g_gi);
    cudaGetSymbolAddress((void**)&pPR,   g_PR);
    cudaGetSymbolAddress((void**)&pPQb,  g_PQb);
    cudaGetSymbolAddress((void**)&pWrt,  g_Wrt);
    cudaGetSymbolAddress((void**)&pWqrt, g_Wqrt);
    cudaGetSymbolAddress((void**)&pWsH,  g_WsH);
    cudaGetSymbolAddress((void**)&pWsL,  g_WsL);
    cudaGetSymbolAddress((void**)&pWhH,  g_WhH);
    cudaGetSymbolAddress((void**)&pWhL,  g_WhL);
    cudaGetSymbolAddress((void**)&pWihH, g_WihH);
    cudaGetSymbolAddress((void**)&pWihL, g_WihL);
    cudaGetSymbolAddress((void**)&pFlag, g_h0nz);

    // dynamic smem sizes
    const int SM64  = (64 * 72 * 2 + 64 * 72  * 2) * (int)sizeof(uint32_t);  //  73.7 KB
    const int SM128 = (64 * 72 * 2 + 64 * 136 * 2) * (int)sizeof(uint32_t);  // 106.5 KB
    cudaFuncSetAttribute(k_gemm_mma<64,  false, false>, cudaFuncAttributeMaxDynamicSharedMemorySize, SM64);
    cudaFuncSetAttribute(k_gemm_mma<128, true,  false>, cudaFuncAttributeMaxDynamicSharedMemorySize, SM128);
    cudaFuncSetAttribute(k_gemm_mma<128, false, true >, cudaFuncAttributeMaxDynamicSharedMemorySize, SM128);

    // 1) flag reset, zero agg + scan h0
    k_flag0<<<1, 1>>>(pFlag);
    k_zero_scan<<<2048, 256>>>(pAgg, h0, Nn * 32, pFlag);

    // 2) weight prep: fp32 transposes for the tiny prep GEMMs, bf16 splits for mma
    k_transpose<<<(64 * 128 + 255) / 256, 256>>>(Wr,  pWrt,  64, 128);
    k_transpose<<<(64 * 128 + 255) / 256, 256>>>(Wqr, pWqrt, 64, 128);
    k_prep_w<<<(64 * 64  + 255) / 256, 256>>>(Ws,   pWsH,  pWsL,  64);
    k_prep_w<<<(64 * 128 + 255) / 256, 256>>>(W_h,  pWhH,  pWhL,  128);
    k_prep_w<<<(64 * 384 + 255) / 256, 256>>>(W_ih, pWihH, pWihL, 384);

    // 3) PR / PQb precompute (fp32)
    k_prep<<<Rv + Bv, 64>>>(rel_emb, b_qr, q_rel, pWrt, pWqrt, pPR, pPQb, Rv, Bv);

    // 4) Xs = hidden @ Ws^T   [N,64]
    int mtiles = (Nn + 63) / 64;
    k_gemm_mma<64, false, false><<<dim3(mtiles, 1), 256, SM64>>>(hidden, pWsH, pWsL, nullptr, pXs, Nn, 64, 64);

    // 5) edge message passing + segment sum
    k_edge<<<(Ev + 7) / 8, 256>>>(hidden, rel_emb, w_alpha, b_alpha,
                                  sub, rel, obj, ebatch, pXs, pPR, pPQb, pAgg, Ev);

    // 6) h_new = relu(agg @ W_h^T)   [N,128]
    k_gemm_mma<128, true, false><<<dim3(mtiles, 1), 256, SM128>>>(pAgg, pWhH, pWhL, nullptr, pHnew, Nn, 128, 128);

    // 7) gi = h_new @ W_ih^T + b_ih  [N,384]  (3 column chunks of 128)
    k_gemm_mma<128, false, true><<<dim3(mtiles, 3), 256, SM128>>>(pHnew, pWihH, pWihL, b_ih, pGi, Nn, 384, 384);

    // 8) GRU gate + final score
    k_gru<<<(Nn + 7) / 8, 256>>>(pGi, b_hh, W_hh, h0, W_final, pFlag, out, Nn);
}